// round 1
// baseline (speedup 1.0000x reference)
#include <cuda_runtime.h>

#define HID 128
#define NN 50000
#define NE 800000
#define NG 64
#define NL 2
#define KC 16

typedef unsigned long long ull;

// Scratch (static device allocation — allowed; no cudaMalloc anywhere)
__device__ float g_X[NN * HID];   // layer input x
__device__ float g_H[NN * HID];   // x + aggr, later gemm2 output
__device__ float g_A[NN * HID];   // gemm1 output
__device__ double g_sum[HID];
__device__ double g_sumsq[HID];
__device__ float g_scale[HID];
__device__ float g_shift[HID];

// ---------------- embedding gather: X[n] = node_emb[x_idx[n]] ----------------
__global__ void embed_kernel(const int* __restrict__ xi, const float* __restrict__ nemb) {
    int i = blockIdx.x * blockDim.x + threadIdx.x;   // float4 index
    if (i >= NN * (HID / 4)) return;
    int n = i >> 5;
    int c = i & 31;
    ((float4*)g_X)[i] = __ldg((const float4*)(nemb + xi[n] * HID) + c);
}

// ---------------- H = X ----------------
__global__ void copy_kernel() {
    int i = blockIdx.x * blockDim.x + threadIdx.x;
    if (i < NN * (HID / 4)) ((float4*)g_H)[i] = ((const float4*)g_X)[i];
}

// ---------------- edge messages: H[dst] += relu(X[src] + edge_emb[attr]) ----------------
// one warp per edge (32 lanes x float4 = 128 floats), 8 edges per warp loop
__global__ void edge_kernel(const int* __restrict__ ei, const int* __restrict__ ea,
                            const float* __restrict__ eemb) {
    int warp = (blockIdx.x * blockDim.x + threadIdx.x) >> 5;
    int lane = threadIdx.x & 31;
    int base = warp * 8;
#pragma unroll
    for (int j = 0; j < 8; j++) {
        int e = base + j;
        if (e >= NE) break;
        int src  = __ldg(ei + e);
        int dst  = __ldg(ei + NE + e);
        int attr = __ldg(ea + e);
        float4 x4 = __ldg((const float4*)(g_X + src * HID) + lane);
        float4 e4 = __ldg((const float4*)(eemb + attr * HID) + lane);
        float4 m;
        m.x = fmaxf(x4.x + e4.x, 0.f);
        m.y = fmaxf(x4.y + e4.y, 0.f);
        m.z = fmaxf(x4.z + e4.z, 0.f);
        m.w = fmaxf(x4.w + e4.w, 0.f);
        float* p = g_H + dst * HID + lane * 4;
        asm volatile("red.global.add.v4.f32 [%0], {%1,%2,%3,%4};"
                     :: "l"(p), "f"(m.x), "f"(m.y), "f"(m.z), "f"(m.w) : "memory");
    }
}

// ---------------- GEMM: C = relu(A @ W + b), A:[NN,128] W:[128,128] ----------------
// 256 threads, 128 rows/block. W fully staged in smem (64KB). A staged in
// duplicated layout (each value stored twice) so FMA2 reads both packed
// operands directly from smem with zero packing MOVs.
#define FMA2(d, a, w) asm("fma.rn.f32x2 %0, %1, %2, %0;" : "+l"(d) : "l"(a), "l"(w))

__global__ void __launch_bounds__(256, 2)
gemm_relu_kernel(const float* __restrict__ A, const float* __restrict__ W,
                 const float* __restrict__ bias, float* __restrict__ C) {
    extern __shared__ float sm[];
    float* Ws = sm;                    // [128][128]
    float* Ad = sm + HID * HID;        // [2][KC][256]  (duplicated rows)
    int tid = threadIdx.x;
    int tx = tid & 15, ty = tid >> 4;
    int rowBase = blockIdx.x * 128;

    // stage W
    for (int i = tid; i < HID * HID / 4; i += 256)
        ((float4*)Ws)[i] = __ldg((const float4*)W + i);

    int lr = tid & 127;       // row within block for the loader
    int lh = tid >> 7;        // which pair of k-slots
    int grow = rowBase + lr;
    const float4* Arow = (const float4*)(A + grow * HID);

    auto loadA = [&](int buf, int kc) {
#pragma unroll
        for (int s = 0; s < 2; s++) {
            int slot = lh * 2 + s;
            float4 v = make_float4(0.f, 0.f, 0.f, 0.f);
            if (grow < NN) v = __ldg(Arow + (kc >> 2) + slot);
            int k0 = slot * 4;
            float* dbase = Ad + (buf * KC + k0) * 256 + 2 * lr;
            *(float2*)(dbase + 0 * 256) = make_float2(v.x, v.x);
            *(float2*)(dbase + 1 * 256) = make_float2(v.y, v.y);
            *(float2*)(dbase + 2 * 256) = make_float2(v.z, v.z);
            *(float2*)(dbase + 3 * 256) = make_float2(v.w, v.w);
        }
    };

    ull acc[8][4];
#pragma unroll
    for (int r = 0; r < 8; r++)
#pragma unroll
        for (int c = 0; c < 4; c++) acc[r][c] = 0ull;

    loadA(0, 0);
    __syncthreads();
    for (int kc = 0; kc < HID; kc += KC) {
        int buf = (kc / KC) & 1;
        if (kc + KC < HID) loadA(buf ^ 1, kc + KC);
#pragma unroll
        for (int kk = 0; kk < KC; kk++) {
            const ulonglong2* ap = (const ulonglong2*)(Ad + (buf * KC + kk) * 256 + ty * 16);
            ulonglong2 a0 = ap[0], a1 = ap[1], a2 = ap[2], a3 = ap[3];
            const ulonglong2* wp = (const ulonglong2*)(Ws + (kc + kk) * HID + tx * 8);
            ulonglong2 w0 = wp[0], w1 = wp[1];
            ull av[8] = {a0.x, a0.y, a1.x, a1.y, a2.x, a2.y, a3.x, a3.y};
            ull wv[4] = {w0.x, w0.y, w1.x, w1.y};
#pragma unroll
            for (int r = 0; r < 8; r++)
#pragma unroll
                for (int c = 0; c < 4; c++)
                    FMA2(acc[r][c], av[r], wv[c]);
        }
        __syncthreads();
    }

    float4 bv0 = __ldg((const float4*)(bias + tx * 8));
    float4 bv1 = __ldg((const float4*)(bias + tx * 8) + 1);
#pragma unroll
    for (int r = 0; r < 8; r++) {
        int row = rowBase + ty * 8 + r;
        if (row >= NN) break;
        float2 f0 = *(float2*)&acc[r][0];
        float2 f1 = *(float2*)&acc[r][1];
        float2 f2 = *(float2*)&acc[r][2];
        float2 f3 = *(float2*)&acc[r][3];
        float4 o0 = make_float4(fmaxf(f0.x + bv0.x, 0.f), fmaxf(f0.y + bv0.y, 0.f),
                                fmaxf(f1.x + bv0.z, 0.f), fmaxf(f1.y + bv0.w, 0.f));
        float4 o1 = make_float4(fmaxf(f2.x + bv1.x, 0.f), fmaxf(f2.y + bv1.y, 0.f),
                                fmaxf(f3.x + bv1.z, 0.f), fmaxf(f3.y + bv1.w, 0.f));
        *(float4*)(C + row * HID + tx * 8) = o0;
        *(float4*)(C + row * HID + tx * 8 + 4) = o1;
    }
}

// ---------------- BatchNorm stats ----------------
__global__ void zero_stats_kernel() {
    int c = threadIdx.x;
    g_sum[c] = 0.0;
    g_sumsq[c] = 0.0;
}

__global__ void stats_kernel(const float* __restrict__ B) {
    __shared__ float ss[256], ss2[256];
    int tid = threadIdx.x;
    int col = tid & 127;
    int half = tid >> 7;
    int r0 = blockIdx.x * 256;
    int r1 = min(r0 + 256, NN);
    float s = 0.f, s2 = 0.f;
    for (int r = r0 + half; r < r1; r += 2) {
        float v = B[r * HID + col];
        s += v;
        s2 += v * v;
    }
    ss[tid] = s;
    ss2[tid] = s2;
    __syncthreads();
    if (half == 0) {
        s += ss[tid + 128];
        s2 += ss2[tid + 128];
        atomicAdd(&g_sum[col], (double)s);
        atomicAdd(&g_sumsq[col], (double)s2);
    }
}

__global__ void finalize_kernel(const float* __restrict__ gw, const float* __restrict__ bw) {
    int c = threadIdx.x;
    double mu = g_sum[c] / (double)NN;
    double var = g_sumsq[c] / (double)NN - mu * mu;
    float sc = (float)((double)gw[c] * rsqrt(var + 1e-5));
    g_scale[c] = sc;
    g_shift[c] = bw[c] - (float)mu * sc;
}

// ---------------- normalize: X = H*scale + shift ----------------
__global__ void norm_kernel() {
    int i = blockIdx.x * blockDim.x + threadIdx.x;
    if (i >= NN * (HID / 4)) return;
    int c = i & 31;
    float4 v = ((const float4*)g_H)[i];
    float4 sc = *(const float4*)(g_scale + c * 4);
    float4 sh = *(const float4*)(g_shift + c * 4);
    v.x = v.x * sc.x + sh.x;
    v.y = v.y * sc.y + sh.y;
    v.z = v.z * sc.z + sh.z;
    v.w = v.w * sc.w + sh.w;
    ((float4*)g_X)[i] = v;
}

// ---------------- pooling ----------------
__global__ void zero_out_kernel(float* out) {
    int i = blockIdx.x * blockDim.x + threadIdx.x;
    if (i < NG * HID) out[i] = 0.f;
}

__global__ void pool_kernel(const int* __restrict__ batch, float* __restrict__ out) {
    int warp = (blockIdx.x * blockDim.x + threadIdx.x) >> 5;
    int lane = threadIdx.x & 31;
    if (warp >= NN) return;
    int g = __ldg(batch + warp);
    float4 v = ((const float4*)g_X)[warp * 32 + lane];
    float* p = out + g * HID + lane * 4;
    asm volatile("red.global.add.v4.f32 [%0], {%1,%2,%3,%4};"
                 :: "l"(p), "f"(v.x), "f"(v.y), "f"(v.z), "f"(v.w) : "memory");
}

// ---------------- host ----------------
extern "C" void kernel_launch(void* const* d_in, const int* in_sizes, int n_in,
                              void* d_out, int out_size) {
    const int*   x_idx      = (const int*)d_in[0];
    const int*   edge_index = (const int*)d_in[1];
    const int*   edge_attr  = (const int*)d_in[2];
    const int*   batch      = (const int*)d_in[3];
    const float* node_emb   = (const float*)d_in[4];
    const float* edge_emb   = (const float*)d_in[5];
    const float* W1         = (const float*)d_in[6];
    const float* b1         = (const float*)d_in[7];
    const float* W2         = (const float*)d_in[8];
    const float* b2         = (const float*)d_in[9];
    const float* bn_g       = (const float*)d_in[10];
    const float* bn_b       = (const float*)d_in[11];
    float* out = (float*)d_out;

    int smemBytes = (HID * HID + 2 * KC * 256) * (int)sizeof(float);  // 96 KB
    cudaFuncSetAttribute(gemm_relu_kernel, cudaFuncAttributeMaxDynamicSharedMemorySize, smemBytes);

    float *Xp, *Hp, *Ap;
    cudaGetSymbolAddress((void**)&Xp, g_X);
    cudaGetSymbolAddress((void**)&Hp, g_H);
    cudaGetSymbolAddress((void**)&Ap, g_A);

    int nf4 = NN * (HID / 4);
    int cpBlocks = (nf4 + 255) / 256;
    int gemmBlocks = (NN + 127) / 128;

    embed_kernel<<<cpBlocks, 256>>>(x_idx, node_emb);

    for (int l = 0; l < NL; l++) {
        copy_kernel<<<cpBlocks, 256>>>();
        edge_kernel<<<NE / 64, 256>>>(edge_index, edge_attr, edge_emb);
        gemm_relu_kernel<<<gemmBlocks, 256, smemBytes>>>(Hp, W1 + l * HID * HID, b1 + l * HID, Ap);
        zero_stats_kernel<<<1, 128>>>();
        gemm_relu_kernel<<<gemmBlocks, 256, smemBytes>>>(Ap, W2 + l * HID * HID, b2 + l * HID, Hp);
        stats_kernel<<<(NN + 255) / 256, 256>>>(Hp);
        finalize_kernel<<<1, 128>>>(bn_g + l * HID, bn_b + l * HID);
        norm_kernel<<<cpBlocks, 256>>>();
    }

    zero_out_kernel<<<(NG * HID + 255) / 256, 256>>>(out);
    pool_kernel<<<NN * 32 / 256, 256>>>(batch, out);
}

// round 5
// speedup vs baseline: 1.1200x; 1.1200x over previous
#include <cuda_runtime.h>
#include <cstdint>

#define HID 128
#define NN 50000
#define NE 800000
#define NG 64
#define NL 2

// ---------------- scratch (static device allocations) ----------------
__device__ float g_X[NN * HID];     // layer input x
__device__ float g_H[NN * HID];     // x + aggr accumulator, later layer output
__device__ float g_A[NN * HID];     // gemm1 output
__device__ double g_sum[HID];
__device__ double g_sumsq[HID];
__device__ float g_scale[HID];
__device__ float g_shift[HID];

__device__ __forceinline__ uint32_t f2tf32(float v) {
    uint32_t o;
    asm("cvt.rna.tf32.f32 %0, %1;" : "=r"(o) : "f"(v));
    return o;
}

#define MMA_TF32(d, a, b) \
    asm volatile("mma.sync.aligned.m16n8k8.row.col.f32.tf32.tf32.f32 " \
        "{%0,%1,%2,%3}, {%4,%5,%6,%7}, {%8,%9}, {%0,%1,%2,%3};" \
        : "+f"((d)[0]), "+f"((d)[1]), "+f"((d)[2]), "+f"((d)[3]) \
        : "r"((a)[0]), "r"((a)[1]), "r"((a)[2]), "r"((a)[3]), \
          "r"((b)[0]), "r"((b)[1]))

// ---------------- embedding gather: X[n] = H[n] = node_emb[x_idx[n]] ----------------
__global__ void embed_kernel(const int* __restrict__ xi, const float* __restrict__ nemb) {
    int i = blockIdx.x * blockDim.x + threadIdx.x;
    if (i >= NN * (HID / 4)) return;
    int n = i >> 5;
    int c = i & 31;
    float4 v = __ldg((const float4*)(nemb + xi[n] * HID) + c);
    ((float4*)g_X)[i] = v;
    ((float4*)g_H)[i] = v;
}

// ---------------- edge messages: H[dst] += relu(X[src] + edge_emb[attr]) ----------------
__global__ void edge_kernel(const int* __restrict__ ei, const int* __restrict__ ea,
                            const float* __restrict__ eemb) {
    int warp = (blockIdx.x * blockDim.x + threadIdx.x) >> 5;
    int lane = threadIdx.x & 31;
    int base = warp * 8;
#pragma unroll
    for (int j = 0; j < 8; j++) {
        int e = base + j;
        if (e >= NE) break;
        int src  = __ldg(ei + e);
        int dst  = __ldg(ei + NE + e);
        int attr = __ldg(ea + e);
        float4 x4 = __ldg((const float4*)(g_X + src * HID) + lane);
        float4 e4 = __ldg((const float4*)(eemb + attr * HID) + lane);
        float4 m;
        m.x = fmaxf(x4.x + e4.x, 0.f);
        m.y = fmaxf(x4.y + e4.y, 0.f);
        m.z = fmaxf(x4.z + e4.z, 0.f);
        m.w = fmaxf(x4.w + e4.w, 0.f);
        float* p = g_H + dst * HID + lane * 4;
        asm volatile("red.global.add.v4.f32 [%0], {%1,%2,%3,%4};"
                     :: "l"(p), "f"(m.x), "f"(m.y), "f"(m.z), "f"(m.w) : "memory");
    }
}

// ---------------- 3xTF32 HMMA GEMM: C = relu(A @ W + bias) ----------------
// Split precision: v = hi + lo (both tf32); acc += hi*lo + lo*hi + hi*hi -> ~fp32.
// Block 512 thr (16 warps), CTA tile 256x128. Warp grid 8(M) x 2(N); warp tile 32x64.
// Smem: As hi/lo [256][36] (K=32 chunk; bank = 4g+tg, conflict-free),
//       Ws hi/lo [128][136] (full W; 136%32==8 -> bank = 8tg+g, conflict-free).
// Total 208KB -> 1 block/SM, 16 warps resident, grid 196 = 1.32 waves.
#define MTILE 256
#define AS_STRIDE 36
#define WS_STRIDE 136
#define AS_WORDS (MTILE * AS_STRIDE)
#define WS_WORDS (128 * WS_STRIDE)
#define SMEM_GEMM ((2 * AS_WORDS + 2 * WS_WORDS) * 4)

__global__ void __launch_bounds__(512, 1)
gemm_mma_kernel(const float* __restrict__ A, const float* __restrict__ W,
                const float* __restrict__ bias, float* __restrict__ C) {
    extern __shared__ char smem[];
    uint32_t* AsH = (uint32_t*)smem;
    uint32_t* AsL = AsH + AS_WORDS;
    uint32_t* WsH = AsL + AS_WORDS;
    uint32_t* WsL = WsH + WS_WORDS;

    int tid = threadIdx.x, wid = tid >> 5, lane = tid & 31;
    int wm = wid & 7, wn = wid >> 3;
    int g = lane >> 2, tg = lane & 3;
    int rowBase = blockIdx.x * MTILE;

    // stage full W [k=128][n=128], split hi/lo
    for (int i = tid; i < 4096; i += 512) {
        int k = i >> 5, c4 = (i & 31) << 2;
        float4 v = __ldg((const float4*)(W + k * HID + c4));
        uint4 h, l;
        h.x = f2tf32(v.x); h.y = f2tf32(v.y); h.z = f2tf32(v.z); h.w = f2tf32(v.w);
        l.x = f2tf32(v.x - __uint_as_float(h.x));
        l.y = f2tf32(v.y - __uint_as_float(h.y));
        l.z = f2tf32(v.z - __uint_as_float(h.z));
        l.w = f2tf32(v.w - __uint_as_float(h.w));
        *(uint4*)(WsH + k * WS_STRIDE + c4) = h;
        *(uint4*)(WsL + k * WS_STRIDE + c4) = l;
    }

    float acc[2][8][4];
#pragma unroll
    for (int mt = 0; mt < 2; mt++)
#pragma unroll
        for (int nt = 0; nt < 8; nt++)
#pragma unroll
            for (int c = 0; c < 4; c++) acc[mt][nt][c] = 0.f;

#pragma unroll
    for (int chunk = 0; chunk < 4; chunk++) {
        if (chunk) __syncthreads();
        // stage A chunk (256 rows x K=32), split hi/lo
        for (int i = tid; i < MTILE * 8; i += 512) {
            int r = i >> 3, c4 = (i & 7) << 2;
            int grow = rowBase + r;
            float4 v = make_float4(0.f, 0.f, 0.f, 0.f);
            if (grow < NN) v = __ldg((const float4*)(A + grow * HID + chunk * 32 + c4));
            uint4 h, l;
            h.x = f2tf32(v.x); h.y = f2tf32(v.y); h.z = f2tf32(v.z); h.w = f2tf32(v.w);
            l.x = f2tf32(v.x - __uint_as_float(h.x));
            l.y = f2tf32(v.y - __uint_as_float(h.y));
            l.z = f2tf32(v.z - __uint_as_float(h.z));
            l.w = f2tf32(v.w - __uint_as_float(h.w));
            *(uint4*)(AsH + r * AS_STRIDE + c4) = h;
            *(uint4*)(AsL + r * AS_STRIDE + c4) = l;
        }
        __syncthreads();

#pragma unroll
        for (int ks = 0; ks < 4; ks++) {
            int k0 = ks * 8;
            uint32_t afH[2][4], afL[2][4];
#pragma unroll
            for (int mt = 0; mt < 2; mt++) {
                int r = wm * 32 + mt * 16 + g;
                afH[mt][0] = AsH[r * AS_STRIDE + k0 + tg];
                afH[mt][1] = AsH[(r + 8) * AS_STRIDE + k0 + tg];
                afH[mt][2] = AsH[r * AS_STRIDE + k0 + tg + 4];
                afH[mt][3] = AsH[(r + 8) * AS_STRIDE + k0 + tg + 4];
                afL[mt][0] = AsL[r * AS_STRIDE + k0 + tg];
                afL[mt][1] = AsL[(r + 8) * AS_STRIDE + k0 + tg];
                afL[mt][2] = AsL[r * AS_STRIDE + k0 + tg + 4];
                afL[mt][3] = AsL[(r + 8) * AS_STRIDE + k0 + tg + 4];
            }
            int kk = chunk * 32 + k0;
            // process nt in halves of 4 to bound bf register pressure
#pragma unroll
            for (int hblk = 0; hblk < 2; hblk++) {
                uint32_t bfH[4][2], bfL[4][2];
#pragma unroll
                for (int q = 0; q < 4; q++) {
                    int nt = hblk * 4 + q;
                    int col = wn * 64 + nt * 8 + g;
                    bfH[q][0] = WsH[(kk + tg) * WS_STRIDE + col];
                    bfH[q][1] = WsH[(kk + tg + 4) * WS_STRIDE + col];
                    bfL[q][0] = WsL[(kk + tg) * WS_STRIDE + col];
                    bfL[q][1] = WsL[(kk + tg + 4) * WS_STRIDE + col];
                }
#pragma unroll
                for (int mt = 0; mt < 2; mt++)
#pragma unroll
                    for (int q = 0; q < 4; q++) {
                        int nt = hblk * 4 + q;
                        MMA_TF32(acc[mt][nt], afH[mt], bfL[q]);
                        MMA_TF32(acc[mt][nt], afL[mt], bfH[q]);
                        MMA_TF32(acc[mt][nt], afH[mt], bfH[q]);
                    }
            }
        }
    }

    // epilogue: bias + relu, v2 stores
#pragma unroll
    for (int mt = 0; mt < 2; mt++) {
        int r0 = rowBase + wm * 32 + mt * 16 + g;
#pragma unroll
        for (int nt = 0; nt < 8; nt++) {
            int col = wn * 64 + nt * 8 + tg * 2;
            float2 bv = __ldg((const float2*)(bias + col));
            if (r0 < NN) {
                float2 o;
                o.x = fmaxf(acc[mt][nt][0] + bv.x, 0.f);
                o.y = fmaxf(acc[mt][nt][1] + bv.y, 0.f);
                *(float2*)(C + r0 * HID + col) = o;
            }
            if (r0 + 8 < NN) {
                float2 o;
                o.x = fmaxf(acc[mt][nt][2] + bv.x, 0.f);
                o.y = fmaxf(acc[mt][nt][3] + bv.y, 0.f);
                *(float2*)(C + (r0 + 8) * HID + col) = o;
            }
        }
    }
}

// ---------------- BatchNorm stats ----------------
__global__ void zero_stats_kernel() {
    int c = threadIdx.x;
    g_sum[c] = 0.0;
    g_sumsq[c] = 0.0;
}

__global__ void stats_kernel(const float* __restrict__ B) {
    __shared__ float ss[256], ss2[256];
    int tid = threadIdx.x;
    int col = tid & 127;
    int half = tid >> 7;
    int r0 = blockIdx.x * 256;
    int r1 = min(r0 + 256, NN);
    float s = 0.f, s2 = 0.f;
    for (int r = r0 + half; r < r1; r += 2) {
        float v = B[r * HID + col];
        s += v;
        s2 += v * v;
    }
    ss[tid] = s;
    ss2[tid] = s2;
    __syncthreads();
    if (half == 0) {
        s += ss[tid + 128];
        s2 += ss2[tid + 128];
        atomicAdd(&g_sum[col], (double)s);
        atomicAdd(&g_sumsq[col], (double)s2);
    }
}

__global__ void finalize_kernel(const float* __restrict__ gw, const float* __restrict__ bw) {
    int c = threadIdx.x;
    double mu = g_sum[c] / (double)NN;
    double var = g_sumsq[c] / (double)NN - mu * mu;
    float sc = (float)((double)gw[c] * rsqrt(var + 1e-5));
    g_scale[c] = sc;
    g_shift[c] = bw[c] - (float)mu * sc;
}

// ---------------- normalize: X = H = Hraw*scale + shift ----------------
__global__ void norm_kernel() {
    int i = blockIdx.x * blockDim.x + threadIdx.x;
    if (i >= NN * (HID / 4)) return;
    int c = i & 31;
    float4 v = ((const float4*)g_H)[i];
    float4 sc = *(const float4*)(g_scale + c * 4);
    float4 sh = *(const float4*)(g_shift + c * 4);
    v.x = v.x * sc.x + sh.x;
    v.y = v.y * sc.y + sh.y;
    v.z = v.z * sc.z + sh.z;
    v.w = v.w * sc.w + sh.w;
    ((float4*)g_X)[i] = v;
    ((float4*)g_H)[i] = v;
}

// ---------------- pooling ----------------
__global__ void zero_out_kernel(float* out) {
    int i = blockIdx.x * blockDim.x + threadIdx.x;
    if (i < NG * HID) out[i] = 0.f;
}

__global__ void pool_kernel(const int* __restrict__ batch, float* __restrict__ out) {
    int warp = (blockIdx.x * blockDim.x + threadIdx.x) >> 5;
    int lane = threadIdx.x & 31;
    if (warp >= NN) return;
    int g = __ldg(batch + warp);
    float4 v = ((const float4*)g_X)[warp * 32 + lane];
    float* p = out + g * HID + lane * 4;
    asm volatile("red.global.add.v4.f32 [%0], {%1,%2,%3,%4};"
                 :: "l"(p), "f"(v.x), "f"(v.y), "f"(v.z), "f"(v.w) : "memory");
}

// ---------------- host ----------------
extern "C" void kernel_launch(void* const* d_in, const int* in_sizes, int n_in,
                              void* d_out, int out_size) {
    const int*   x_idx      = (const int*)d_in[0];
    const int*   edge_index = (const int*)d_in[1];
    const int*   edge_attr  = (const int*)d_in[2];
    const int*   batch      = (const int*)d_in[3];
    const float* node_emb   = (const float*)d_in[4];
    const float* edge_emb   = (const float*)d_in[5];
    const float* W1         = (const float*)d_in[6];
    const float* b1         = (const float*)d_in[7];
    const float* W2         = (const float*)d_in[8];
    const float* b2         = (const float*)d_in[9];
    const float* bn_g       = (const float*)d_in[10];
    const float* bn_b       = (const float*)d_in[11];
    float* out = (float*)d_out;

    cudaFuncSetAttribute(gemm_mma_kernel, cudaFuncAttributeMaxDynamicSharedMemorySize, SMEM_GEMM);

    float *Xp, *Hp, *Ap;
    cudaGetSymbolAddress((void**)&Xp, g_X);
    cudaGetSymbolAddress((void**)&Hp, g_H);
    cudaGetSymbolAddress((void**)&Ap, g_A);

    int nf4 = NN * (HID / 4);
    int cpBlocks = (nf4 + 255) / 256;
    int gemmBlocks = (NN + MTILE - 1) / MTILE;

    embed_kernel<<<cpBlocks, 256>>>(x_idx, node_emb);

    for (int l = 0; l < NL; l++) {
        edge_kernel<<<NE / 64, 256>>>(edge_index, edge_attr, edge_emb);
        gemm_mma_kernel<<<gemmBlocks, 512, SMEM_GEMM>>>(Hp, W1 + l * HID * HID, b1 + l * HID, Ap);
        zero_stats_kernel<<<1, 128>>>();
        gemm_mma_kernel<<<gemmBlocks, 512, SMEM_GEMM>>>(Ap, W2 + l * HID * HID, b2 + l * HID, Hp);
        stats_kernel<<<(NN + 255) / 256, 256>>>(Hp);
        finalize_kernel<<<1, 128>>>(bn_g + l * HID, bn_b + l * HID);
        norm_kernel<<<cpBlocks, 256>>>();
    }

    zero_out_kernel<<<(NG * HID + 255) / 256, 256>>>(out);
    pool_kernel<<<NN * 32 / 256, 256>>>(batch, out);
}

// round 6
// speedup vs baseline: 1.1321x; 1.0108x over previous
#include <cuda_runtime.h>
#include <cstdint>

#define HID 128
#define NN 50000
#define NE 800000
#define NG 64
#define NL 2

// ---------------- scratch (static device allocations) ----------------
__device__ __align__(16) float g_X[NN * HID];     // layer0 input (raw), layer1 raw output
__device__ __align__(16) float g_H[NN * HID];     // layer0 raw output / layer1 input
__device__ __align__(16) float g_A[NN * HID];     // gemm1 output
__device__ __align__(16) float g_AGG0[NN * HID];  // edge aggregation layer 0
__device__ __align__(16) float g_AGG1[NN * HID];  // edge aggregation layer 1
__device__ double g_sum[HID];
__device__ double g_sumsq[HID];
__device__ __align__(16) float g_scale[HID];
__device__ __align__(16) float g_shift[HID];

__device__ __forceinline__ uint32_t f2tf32(float v) {
    uint32_t o;
    asm("cvt.rna.tf32.f32 %0, %1;" : "=r"(o) : "f"(v));
    return o;
}

#define MMA_TF32(d, a, b) \
    asm volatile("mma.sync.aligned.m16n8k8.row.col.f32.tf32.tf32.f32 " \
        "{%0,%1,%2,%3}, {%4,%5,%6,%7}, {%8,%9}, {%0,%1,%2,%3};" \
        : "+f"((d)[0]), "+f"((d)[1]), "+f"((d)[2]), "+f"((d)[3]) \
        : "r"((a)[0]), "r"((a)[1]), "r"((a)[2]), "r"((a)[3]), \
          "r"((b)[0]), "r"((b)[1]))

// ---------------- embed: X = node_emb[x_idx]; zero AGG0/AGG1; init scale/shift ----------------
__global__ void embed_kernel(const int* __restrict__ xi, const float* __restrict__ nemb) {
    int i = blockIdx.x * blockDim.x + threadIdx.x;
    if (i < HID) { g_scale[i] = 1.f; g_shift[i] = 0.f; }
    if (i >= NN * (HID / 4)) return;
    int n = i >> 5;
    int c = i & 31;
    float4 v = __ldg((const float4*)(nemb + xi[n] * HID) + c);
    ((float4*)g_X)[i] = v;
    float4 z = make_float4(0.f, 0.f, 0.f, 0.f);
    ((float4*)g_AGG0)[i] = z;
    ((float4*)g_AGG1)[i] = z;
}

// ---------------- edge: AGG[dst] += relu(norm(X[src]) + edge_emb[attr]) ----------------
__global__ void edge_kernel(const float* __restrict__ X, float* __restrict__ AGG,
                            const int* __restrict__ ei, const int* __restrict__ ea,
                            const float* __restrict__ eemb) {
    int warp = (blockIdx.x * blockDim.x + threadIdx.x) >> 5;
    int lane = threadIdx.x & 31;
    float4 sc = *(const float4*)(g_scale + lane * 4);
    float4 sh = *(const float4*)(g_shift + lane * 4);
    int base = warp * 8;
#pragma unroll
    for (int j = 0; j < 8; j++) {
        int e = base + j;
        if (e >= NE) break;
        int src  = __ldg(ei + e);
        int dst  = __ldg(ei + NE + e);
        int attr = __ldg(ea + e);
        float4 x4 = __ldg((const float4*)(X + src * HID) + lane);
        float4 e4 = __ldg((const float4*)(eemb + attr * HID) + lane);
        float4 m;
        m.x = fmaxf(fmaf(x4.x, sc.x, sh.x) + e4.x, 0.f);
        m.y = fmaxf(fmaf(x4.y, sc.y, sh.y) + e4.y, 0.f);
        m.z = fmaxf(fmaf(x4.z, sc.z, sh.z) + e4.z, 0.f);
        m.w = fmaxf(fmaf(x4.w, sc.w, sh.w) + e4.w, 0.f);
        float* p = AGG + dst * HID + lane * 4;
        asm volatile("red.global.add.v4.f32 [%0], {%1,%2,%3,%4};"
                     :: "l"(p), "f"(m.x), "f"(m.y), "f"(m.z), "f"(m.w) : "memory");
    }
}

// ---------------- 3xTF32 HMMA GEMM: C = relu(A' @ W + bias) ----------------
// NORM_AGG: A' = norm(A) + AGG (gemm1).  STATS: accumulate BN col stats (gemm2).
// Block 512 thr, CTA tile 256x128, warp grid 8Mx2N, warp tile 32x64.
#define MTILE 256
#define AS_STRIDE 36
#define WS_STRIDE 136
#define AS_WORDS (MTILE * AS_STRIDE)
#define WS_WORDS (128 * WS_STRIDE)
#define STAT_OFF (2 * AS_WORDS + 2 * WS_WORDS)
#define SMEM_GEMM ((STAT_OFF + 256) * 4)

template <bool NORM_AGG, bool STATS>
__global__ void __launch_bounds__(512, 1)
gemm_mma_kernel(const float* __restrict__ A, const float* __restrict__ AGG,
                const float* __restrict__ W, const float* __restrict__ bias,
                float* __restrict__ C) {
    extern __shared__ char smem[];
    uint32_t* AsH = (uint32_t*)smem;
    uint32_t* AsL = AsH + AS_WORDS;
    uint32_t* WsH = AsL + AS_WORDS;
    uint32_t* WsL = WsH + WS_WORDS;
    float* ssum = (float*)(AsH + STAT_OFF);
    float* ssq = ssum + 128;

    int tid = threadIdx.x, wid = tid >> 5, lane = tid & 31;
    int wm = wid & 7, wn = wid >> 3;
    int g = lane >> 2, tg = lane & 3;
    int rowBase = blockIdx.x * MTILE;

    if (STATS && tid < 256) ssum[tid] = 0.f;   // covers ssum+ssq

    // stage full W [k][n], split hi/lo
    for (int i = tid; i < 4096; i += 512) {
        int k = i >> 5, c4 = (i & 31) << 2;
        float4 v = __ldg((const float4*)(W + k * HID + c4));
        uint4 h, l;
        h.x = f2tf32(v.x); h.y = f2tf32(v.y); h.z = f2tf32(v.z); h.w = f2tf32(v.w);
        l.x = f2tf32(v.x - __uint_as_float(h.x));
        l.y = f2tf32(v.y - __uint_as_float(h.y));
        l.z = f2tf32(v.z - __uint_as_float(h.z));
        l.w = f2tf32(v.w - __uint_as_float(h.w));
        *(uint4*)(WsH + k * WS_STRIDE + c4) = h;
        *(uint4*)(WsL + k * WS_STRIDE + c4) = l;
    }

    float acc[2][8][4];
#pragma unroll
    for (int mt = 0; mt < 2; mt++)
#pragma unroll
        for (int nt = 0; nt < 8; nt++)
#pragma unroll
            for (int c = 0; c < 4; c++) acc[mt][nt][c] = 0.f;

#pragma unroll
    for (int chunk = 0; chunk < 4; chunk++) {
        if (chunk) __syncthreads();
        for (int i = tid; i < MTILE * 8; i += 512) {
            int r = i >> 3, c4 = (i & 7) << 2;
            int grow = rowBase + r;
            float4 v = make_float4(0.f, 0.f, 0.f, 0.f);
            if (grow < NN) {
                v = __ldg((const float4*)(A + grow * HID + chunk * 32 + c4));
                if (NORM_AGG) {
                    float4 sc = *(const float4*)(g_scale + chunk * 32 + c4);
                    float4 sh = *(const float4*)(g_shift + chunk * 32 + c4);
                    float4 ag = __ldg((const float4*)(AGG + grow * HID + chunk * 32 + c4));
                    v.x = fmaf(v.x, sc.x, sh.x) + ag.x;
                    v.y = fmaf(v.y, sc.y, sh.y) + ag.y;
                    v.z = fmaf(v.z, sc.z, sh.z) + ag.z;
                    v.w = fmaf(v.w, sc.w, sh.w) + ag.w;
                }
            }
            uint4 h, l;
            h.x = f2tf32(v.x); h.y = f2tf32(v.y); h.z = f2tf32(v.z); h.w = f2tf32(v.w);
            l.x = f2tf32(v.x - __uint_as_float(h.x));
            l.y = f2tf32(v.y - __uint_as_float(h.y));
            l.z = f2tf32(v.z - __uint_as_float(h.z));
            l.w = f2tf32(v.w - __uint_as_float(h.w));
            *(uint4*)(AsH + r * AS_STRIDE + c4) = h;
            *(uint4*)(AsL + r * AS_STRIDE + c4) = l;
        }
        __syncthreads();

#pragma unroll
        for (int ks = 0; ks < 4; ks++) {
            int k0 = ks * 8;
            uint32_t afH[2][4], afL[2][4];
#pragma unroll
            for (int mt = 0; mt < 2; mt++) {
                int r = wm * 32 + mt * 16 + g;
                afH[mt][0] = AsH[r * AS_STRIDE + k0 + tg];
                afH[mt][1] = AsH[(r + 8) * AS_STRIDE + k0 + tg];
                afH[mt][2] = AsH[r * AS_STRIDE + k0 + tg + 4];
                afH[mt][3] = AsH[(r + 8) * AS_STRIDE + k0 + tg + 4];
                afL[mt][0] = AsL[r * AS_STRIDE + k0 + tg];
                afL[mt][1] = AsL[(r + 8) * AS_STRIDE + k0 + tg];
                afL[mt][2] = AsL[r * AS_STRIDE + k0 + tg + 4];
                afL[mt][3] = AsL[(r + 8) * AS_STRIDE + k0 + tg + 4];
            }
            int kk = chunk * 32 + k0;
#pragma unroll
            for (int hblk = 0; hblk < 2; hblk++) {
                uint32_t bfH[4][2], bfL[4][2];
#pragma unroll
                for (int q = 0; q < 4; q++) {
                    int nt = hblk * 4 + q;
                    int col = wn * 64 + nt * 8 + g;
                    bfH[q][0] = WsH[(kk + tg) * WS_STRIDE + col];
                    bfH[q][1] = WsH[(kk + tg + 4) * WS_STRIDE + col];
                    bfL[q][0] = WsL[(kk + tg) * WS_STRIDE + col];
                    bfL[q][1] = WsL[(kk + tg + 4) * WS_STRIDE + col];
                }
#pragma unroll
                for (int mt = 0; mt < 2; mt++)
#pragma unroll
                    for (int q = 0; q < 4; q++) {
                        int nt = hblk * 4 + q;
                        MMA_TF32(acc[mt][nt], afH[mt], bfL[q]);
                        MMA_TF32(acc[mt][nt], afL[mt], bfH[q]);
                        MMA_TF32(acc[mt][nt], afH[mt], bfH[q]);
                    }
            }
        }
    }
    if (STATS) __syncthreads();   // ssum zeroing + all As reads done before epilogue atomics

    // epilogue: bias + relu, stores, optional column stats
#pragma unroll
    for (int nt = 0; nt < 8; nt++) {
        int col = wn * 64 + nt * 8 + tg * 2;
        float2 bv = __ldg((const float2*)(bias + col));
        float s0 = 0.f, s1 = 0.f, q0 = 0.f, q1 = 0.f;
#pragma unroll
        for (int mt = 0; mt < 2; mt++) {
            int r0 = rowBase + wm * 32 + mt * 16 + g;
            float2 oa, ob;
            oa.x = fmaxf(acc[mt][nt][0] + bv.x, 0.f);
            oa.y = fmaxf(acc[mt][nt][1] + bv.y, 0.f);
            ob.x = fmaxf(acc[mt][nt][2] + bv.x, 0.f);
            ob.y = fmaxf(acc[mt][nt][3] + bv.y, 0.f);
            if (r0 < NN) {
                *(float2*)(C + r0 * HID + col) = oa;
                if (STATS) { s0 += oa.x; q0 += oa.x * oa.x; s1 += oa.y; q1 += oa.y * oa.y; }
            }
            if (r0 + 8 < NN) {
                *(float2*)(C + (r0 + 8) * HID + col) = ob;
                if (STATS) { s0 += ob.x; q0 += ob.x * ob.x; s1 += ob.y; q1 += ob.y * ob.y; }
            }
        }
        if (STATS) {
#pragma unroll
            for (int m = 16; m >= 4; m >>= 1) {
                s0 += __shfl_xor_sync(0xffffffff, s0, m);
                s1 += __shfl_xor_sync(0xffffffff, s1, m);
                q0 += __shfl_xor_sync(0xffffffff, q0, m);
                q1 += __shfl_xor_sync(0xffffffff, q1, m);
            }
            if (lane < 4) {
                int c0 = wn * 64 + nt * 8 + lane * 2;
                atomicAdd(&ssum[c0], s0);
                atomicAdd(&ssum[c0 + 1], s1);
                atomicAdd(&ssq[c0], q0);
                atomicAdd(&ssq[c0 + 1], q1);
            }
        }
    }
    if (STATS) {
        __syncthreads();
        if (tid < 128) {
            atomicAdd(&g_sum[tid], (double)ssum[tid]);
            atomicAdd(&g_sumsq[tid], (double)ssq[tid]);
        }
    }
}

// ---------------- finalize: scale/shift from stats; reset accumulators ----------------
__global__ void finalize_kernel(const float* __restrict__ gw, const float* __restrict__ bw) {
    int c = threadIdx.x;
    double mu = g_sum[c] / (double)NN;
    double var = g_sumsq[c] / (double)NN - mu * mu;
    float sc = (float)((double)gw[c] * rsqrt(var + 1e-5));
    g_scale[c] = sc;
    g_shift[c] = bw[c] - (float)mu * sc;
    g_sum[c] = 0.0;
    g_sumsq[c] = 0.0;
}

// ---------------- pooling (applies final norm inline) ----------------
__global__ void zero_out_kernel(float* out) {
    int i = blockIdx.x * blockDim.x + threadIdx.x;
    if (i < NG * HID) out[i] = 0.f;
}

__global__ void pool_kernel(const float* __restrict__ X, const int* __restrict__ batch,
                            float* __restrict__ out) {
    int warp = (blockIdx.x * blockDim.x + threadIdx.x) >> 5;
    int lane = threadIdx.x & 31;
    if (warp >= NN) return;
    float4 sc = *(const float4*)(g_scale + lane * 4);
    float4 sh = *(const float4*)(g_shift + lane * 4);
    int g = __ldg(batch + warp);
    float4 v = __ldg((const float4*)(X + warp * HID) + lane);
    v.x = fmaf(v.x, sc.x, sh.x);
    v.y = fmaf(v.y, sc.y, sh.y);
    v.z = fmaf(v.z, sc.z, sh.z);
    v.w = fmaf(v.w, sc.w, sh.w);
    float* p = out + g * HID + lane * 4;
    asm volatile("red.global.add.v4.f32 [%0], {%1,%2,%3,%4};"
                 :: "l"(p), "f"(v.x), "f"(v.y), "f"(v.z), "f"(v.w) : "memory");
}

// ---------------- host ----------------
extern "C" void kernel_launch(void* const* d_in, const int* in_sizes, int n_in,
                              void* d_out, int out_size) {
    const int*   x_idx      = (const int*)d_in[0];
    const int*   edge_index = (const int*)d_in[1];
    const int*   edge_attr  = (const int*)d_in[2];
    const int*   batch      = (const int*)d_in[3];
    const float* node_emb   = (const float*)d_in[4];
    const float* edge_emb   = (const float*)d_in[5];
    const float* W1         = (const float*)d_in[6];
    const float* b1         = (const float*)d_in[7];
    const float* W2         = (const float*)d_in[8];
    const float* b2         = (const float*)d_in[9];
    const float* bn_g       = (const float*)d_in[10];
    const float* bn_b       = (const float*)d_in[11];
    float* out = (float*)d_out;

    cudaFuncSetAttribute(gemm_mma_kernel<true, false>,
                         cudaFuncAttributeMaxDynamicSharedMemorySize, SMEM_GEMM);
    cudaFuncSetAttribute(gemm_mma_kernel<false, true>,
                         cudaFuncAttributeMaxDynamicSharedMemorySize, SMEM_GEMM);

    float *Xp, *Hp, *Ap, *Ag0, *Ag1;
    cudaGetSymbolAddress((void**)&Xp, g_X);
    cudaGetSymbolAddress((void**)&Hp, g_H);
    cudaGetSymbolAddress((void**)&Ap, g_A);
    cudaGetSymbolAddress((void**)&Ag0, g_AGG0);
    cudaGetSymbolAddress((void**)&Ag1, g_AGG1);

    int nf4 = NN * (HID / 4);
    int cpBlocks = (nf4 + 255) / 256;
    int gemmBlocks = (NN + MTILE - 1) / MTILE;

    embed_kernel<<<cpBlocks, 256>>>(x_idx, node_emb);

    const float* Xin[NL] = {Xp, Hp};
    float* Xout[NL] = {Hp, Xp};
    float* Agg[NL] = {Ag0, Ag1};

    for (int l = 0; l < NL; l++) {
        edge_kernel<<<NE / 64, 256>>>(Xin[l], Agg[l], edge_index, edge_attr, edge_emb);
        gemm_mma_kernel<true, false><<<gemmBlocks, 512, SMEM_GEMM>>>(
            Xin[l], Agg[l], W1 + l * HID * HID, b1 + l * HID, Ap);
        gemm_mma_kernel<false, true><<<gemmBlocks, 512, SMEM_GEMM>>>(
            Ap, nullptr, W2 + l * HID * HID, b2 + l * HID, Xout[l]);
        finalize_kernel<<<1, 128>>>(bn_g + l * HID, bn_b + l * HID);
    }

    zero_out_kernel<<<(NG * HID + 255) / 256, 256>>>(out);
    pool_kernel<<<NN * 32 / 256, 256>>>(Xout[NL - 1], batch, out);
}